// round 1
// baseline (speedup 1.0000x reference)
#include <cuda_runtime.h>
#include <cuda_bf16.h>
#include <cstdint>

#define D 64
#define MAX_N 50000
#define MAX_E 800000

// Scratch (no cudaMalloc allowed). float4 arrays guarantee 16B alignment for RED.128.
__device__ float4 g_sum4[MAX_N * (D / 4)];
__device__ float4 g_h1_4[MAX_N * (D / 4)];
__device__ float  g_deg[MAX_N];

// ---------------------------------------------------------------------------
// Zero the accumulator (and optionally the degree array).
// ---------------------------------------------------------------------------
__global__ void zero_kernel(float4* __restrict__ sum4, float* __restrict__ deg,
                            int n_nodes, int zero_deg) {
    int t = blockIdx.x * blockDim.x + threadIdx.x;
    int nsum4 = n_nodes * (D / 4);
    if (t < nsum4) sum4[t] = make_float4(0.f, 0.f, 0.f, 0.f);
    if (zero_deg && t < n_nodes) deg[t] = 0.f;
}

// ---------------------------------------------------------------------------
// Edge scatter: sum[dst] += x[src], 16 threads per edge, one float4 each.
// Optionally accumulates in-degree (first sub-thread of each edge).
// ---------------------------------------------------------------------------
__global__ void scatter_kernel(const float4* __restrict__ xin,
                               const int* __restrict__ src,
                               const int* __restrict__ dst,
                               float4* __restrict__ sum4,
                               float* __restrict__ deg,
                               int n_edges, int add_deg) {
    long long t = (long long)blockIdx.x * blockDim.x + threadIdx.x;
    long long total = (long long)n_edges * 16;
    if (t >= total) return;
    int e = (int)(t >> 4);
    int i = (int)(t & 15);
    int s = __ldg(&src[e]);
    int d = __ldg(&dst[e]);
    float4 v = __ldg(&xin[(size_t)s * 16 + i]);
    atomicAdd(&sum4[(size_t)d * 16 + i], v);   // RED.128 on sm_90+
    if (add_deg && i == 0) atomicAdd(&deg[d], 1.0f);
}

// ---------------------------------------------------------------------------
// Fused SAGE layer: out[n] = (relu?)( x[n] @ Wself + (sum[n]/max(deg,1)) @ Wneigh + b )
// Block: 256 threads. Tile: 64 nodes. Thread = 4 nodes x 4 output cols.
// SMEM: Wself(16K) + Wneigh(16K) + bias(256B) + xtile(16K) + mtile(16K) = 64.25 KB.
// ---------------------------------------------------------------------------
#define SAGE_SMEM_FLOATS (4096 + 4096 + 64 + 4096 + 4096)
#define SAGE_SMEM_BYTES  (SAGE_SMEM_FLOATS * 4)

__global__ void __launch_bounds__(256) sage_kernel(
    const float* __restrict__ hin,
    const float* __restrict__ Wself,
    const float* __restrict__ Wneigh,
    const float* __restrict__ bias,
    const float4* __restrict__ sum4,
    const float* __restrict__ deg,
    float* __restrict__ hout,
    int n_nodes, int do_relu)
{
    extern __shared__ float sm[];
    float* sWs = sm;                    // [64][64]
    float* sWn = sm + 4096;             // [64][64]
    float* sB  = sm + 8192;             // [64]
    float* sX  = sm + 8256;             // [64 nodes][64]
    float* sM  = sm + 8256 + 4096;      // [64 nodes][64]

    const int tid = threadIdx.x;

    for (int i = tid; i < 4096; i += 256) {
        sWs[i] = Wself[i];
        sWn[i] = Wneigh[i];
    }
    if (tid < 64) sB[tid] = bias[tid];
    __syncthreads();

    const int cg  = tid & 15;   // column group: cols [cg*4, cg*4+4)
    const int row = tid >> 4;   // thread row: nodes [row*4, row*4+4) within tile

    const int numTiles = (n_nodes + 63) >> 6;
    for (int tile = blockIdx.x; tile < numTiles; tile += gridDim.x) {
        const int node0 = tile << 6;

        // Stage 64 node rows of x and mean into SMEM (float4 coalesced).
        for (int i = tid; i < 1024; i += 256) {       // i indexes float4 in [64][16]
            int nl = i >> 4;
            int c4 = i & 15;
            int n = node0 + nl;
            float4 xv = make_float4(0.f, 0.f, 0.f, 0.f);
            float4 mv = make_float4(0.f, 0.f, 0.f, 0.f);
            if (n < n_nodes) {
                xv = __ldg((const float4*)hin + (size_t)n * 16 + c4);
                float r = 1.0f / fmaxf(__ldg(&deg[n]), 1.0f);
                float4 s = sum4[(size_t)n * 16 + c4];
                mv = make_float4(s.x * r, s.y * r, s.z * r, s.w * r);
            }
            ((float4*)sX)[i] = xv;
            ((float4*)sM)[i] = mv;
        }
        __syncthreads();

        float4 bv = ((float4*)sB)[cg];
        float4 acc[4];
#pragma unroll
        for (int t4 = 0; t4 < 4; t4++) acc[t4] = bv;

#pragma unroll 4
        for (int k = 0; k < D; k++) {
            float4 ws = ((const float4*)sWs)[k * 16 + cg];
            float4 wn = ((const float4*)sWn)[k * 16 + cg];
#pragma unroll
            for (int t4 = 0; t4 < 4; t4++) {
                int nl = row * 4 + t4;
                float xv = sX[nl * D + k];
                float mv = sM[nl * D + k];
                acc[t4].x = fmaf(xv, ws.x, fmaf(mv, wn.x, acc[t4].x));
                acc[t4].y = fmaf(xv, ws.y, fmaf(mv, wn.y, acc[t4].y));
                acc[t4].z = fmaf(xv, ws.z, fmaf(mv, wn.z, acc[t4].z));
                acc[t4].w = fmaf(xv, ws.w, fmaf(mv, wn.w, acc[t4].w));
            }
        }

#pragma unroll
        for (int t4 = 0; t4 < 4; t4++) {
            int n = node0 + row * 4 + t4;
            if (n < n_nodes) {
                float4 o = acc[t4];
                if (do_relu) {
                    o.x = fmaxf(o.x, 0.f);
                    o.y = fmaxf(o.y, 0.f);
                    o.z = fmaxf(o.z, 0.f);
                    o.w = fmaxf(o.w, 0.f);
                }
                ((float4*)hout)[(size_t)n * 16 + cg] = o;
            }
        }
        __syncthreads();
    }
}

// ---------------------------------------------------------------------------
// Launch: 6 graph-capturable kernels.
// ---------------------------------------------------------------------------
extern "C" void kernel_launch(void* const* d_in, const int* in_sizes, int n_in,
                              void* d_out, int out_size) {
    const float* x   = (const float*)d_in[0];
    const int*   src = (const int*)d_in[1];
    const int*   dst = (const int*)d_in[2];
    const float* W1s = (const float*)d_in[3];
    const float* W1n = (const float*)d_in[4];
    const float* b1  = (const float*)d_in[5];
    const float* W2s = (const float*)d_in[6];
    const float* W2n = (const float*)d_in[7];
    const float* b2  = (const float*)d_in[8];
    float* out = (float*)d_out;

    const int N = in_sizes[0] / D;
    const int E = in_sizes[1];

    float4* sum4; float4* h1_4; float* deg;
    cudaGetSymbolAddress((void**)&sum4, g_sum4);
    cudaGetSymbolAddress((void**)&h1_4, g_h1_4);
    cudaGetSymbolAddress((void**)&deg,  g_deg);
    float* h1 = (float*)h1_4;

    cudaFuncSetAttribute(sage_kernel,
                         cudaFuncAttributeMaxDynamicSharedMemorySize,
                         SAGE_SMEM_BYTES);

    const int zb = (N * (D / 4) + 255) / 256;
    const int sb = (int)(((long long)E * 16 + 255) / 256);
    const int gb = 148 * 3;   // persistent-ish grid for the GEMM kernel

    // Layer 1
    zero_kernel<<<zb, 256>>>(sum4, deg, N, 1);
    scatter_kernel<<<sb, 256>>>((const float4*)x, src, dst, sum4, deg, E, 1);
    sage_kernel<<<gb, 256, SAGE_SMEM_BYTES>>>(x, W1s, W1n, b1, sum4, deg, h1, N, 1);

    // Layer 2 (degree unchanged)
    zero_kernel<<<zb, 256>>>(sum4, deg, N, 0);
    scatter_kernel<<<sb, 256>>>((const float4*)h1, src, dst, sum4, deg, E, 0);
    sage_kernel<<<gb, 256, SAGE_SMEM_BYTES>>>(h1, W2s, W2n, b2, sum4, deg, out, N, 0);
}

// round 2
// speedup vs baseline: 1.1878x; 1.1878x over previous
#include <cuda_runtime.h>
#include <cuda_bf16.h>
#include <cstdint>

#define D 64
#define MAX_N 50000
#define MAX_E 800000
#define NB_SCAN ((MAX_N + 255) / 256)

// Scratch (no cudaMalloc allowed). float4 arrays guarantee 16B alignment.
__device__ float4 g_h1_4[MAX_N * (D / 4)];      // layer-1 activations
__device__ float4 g_mean4[MAX_N * (D / 4)];     // aggregated mean features
__device__ int    g_degi[MAX_N];                // integer in-degree
__device__ int    g_row_start[MAX_N + 1];       // CSR row offsets (by dst)
__device__ int    g_cursor[MAX_N];              // fill cursors
__device__ float  g_inv_deg[MAX_N];             // 1/max(deg,1)
__device__ int    g_esrc[MAX_E];                // CSR column indices (src)
__device__ int    g_block_sum[NB_SCAN];         // scan partials
__device__ int    g_block_off[NB_SCAN];         // scan block offsets

// ---------------------------------------------------------------------------
// CSR build
// ---------------------------------------------------------------------------
__global__ void zero_deg_kernel(int* __restrict__ degi, int n) {
    int i = blockIdx.x * blockDim.x + threadIdx.x;
    if (i < n) degi[i] = 0;
}

__global__ void count_kernel(const int* __restrict__ dst, int* __restrict__ degi,
                             int n_edges) {
    int e = blockIdx.x * blockDim.x + threadIdx.x;
    if (e < n_edges) atomicAdd(&degi[__ldg(&dst[e])], 1);
}

// Phase 1: per-block exclusive scan of degrees; store local excl, block sums.
__global__ void scan1_kernel(const int* __restrict__ degi,
                             int* __restrict__ row_start,
                             int* __restrict__ block_sum, int n) {
    __shared__ int sh[256];
    int tid = threadIdx.x;
    int i = blockIdx.x * 256 + tid;
    int d = (i < n) ? degi[i] : 0;
    sh[tid] = d;
    __syncthreads();
#pragma unroll
    for (int off = 1; off < 256; off <<= 1) {
        int v = (tid >= off) ? sh[tid - off] : 0;
        __syncthreads();
        sh[tid] += v;
        __syncthreads();
    }
    if (i < n) row_start[i] = sh[tid] - d;      // local exclusive
    if (tid == 255) block_sum[blockIdx.x] = sh[255];
}

// Phase 2: single block scans the block sums (NB_SCAN <= 256).
__global__ void scan2_kernel(const int* __restrict__ block_sum,
                             int* __restrict__ block_off, int nb) {
    __shared__ int sh[256];
    int tid = threadIdx.x;
    int d = (tid < nb) ? block_sum[tid] : 0;
    sh[tid] = d;
    __syncthreads();
#pragma unroll
    for (int off = 1; off < 256; off <<= 1) {
        int v = (tid >= off) ? sh[tid - off] : 0;
        __syncthreads();
        sh[tid] += v;
        __syncthreads();
    }
    if (tid < nb) block_off[tid] = sh[tid] - d; // exclusive
}

// Phase 3: add block offsets, init cursors and inv_deg, cap row_start[n].
__global__ void scan3_kernel(int* __restrict__ row_start,
                             int* __restrict__ cursor,
                             float* __restrict__ inv_deg,
                             const int* __restrict__ degi,
                             const int* __restrict__ block_off,
                             int n, int n_edges) {
    int i = blockIdx.x * 256 + threadIdx.x;
    if (i < n) {
        int rs = row_start[i] + block_off[blockIdx.x];
        row_start[i] = rs;
        cursor[i] = rs;
        inv_deg[i] = 1.0f / fmaxf((float)degi[i], 1.0f);
    }
    if (i == 0) row_start[n] = n_edges;
}

__global__ void fill_kernel(const int* __restrict__ src,
                            const int* __restrict__ dst,
                            int* __restrict__ cursor,
                            int* __restrict__ esrc, int n_edges) {
    int e = blockIdx.x * blockDim.x + threadIdx.x;
    if (e < n_edges) {
        int p = atomicAdd(&cursor[__ldg(&dst[e])], 1);
        esrc[p] = __ldg(&src[e]);
    }
}

// ---------------------------------------------------------------------------
// Gather-mean: one warp per node; lane l accumulates cols {2l, 2l+1}.
// mean[n] = (1/max(deg,1)) * sum_{e in CSR[n]} x[esrc[e]]
// ---------------------------------------------------------------------------
__global__ void __launch_bounds__(256) gather_kernel(
    const float2* __restrict__ xin,
    const int* __restrict__ row_start,
    const int* __restrict__ esrc,
    const float* __restrict__ inv_deg,
    float2* __restrict__ mean, int n_nodes)
{
    int warp = (blockIdx.x * blockDim.x + threadIdx.x) >> 5;
    int lane = threadIdx.x & 31;
    if (warp >= n_nodes) return;

    int beg = __ldg(&row_start[warp]);
    int end = __ldg(&row_start[warp + 1]);

    float2 a0 = {0.f, 0.f}, a1 = {0.f, 0.f}, a2 = {0.f, 0.f}, a3 = {0.f, 0.f};
    int e = beg;
    for (; e + 4 <= end; e += 4) {
        int s0 = __ldg(&esrc[e]);
        int s1 = __ldg(&esrc[e + 1]);
        int s2 = __ldg(&esrc[e + 2]);
        int s3 = __ldg(&esrc[e + 3]);
        float2 v0 = __ldg(&xin[(size_t)s0 * 32 + lane]);
        float2 v1 = __ldg(&xin[(size_t)s1 * 32 + lane]);
        float2 v2 = __ldg(&xin[(size_t)s2 * 32 + lane]);
        float2 v3 = __ldg(&xin[(size_t)s3 * 32 + lane]);
        a0.x += v0.x; a0.y += v0.y;
        a1.x += v1.x; a1.y += v1.y;
        a2.x += v2.x; a2.y += v2.y;
        a3.x += v3.x; a3.y += v3.y;
    }
    for (; e < end; e++) {
        int s = __ldg(&esrc[e]);
        float2 v = __ldg(&xin[(size_t)s * 32 + lane]);
        a0.x += v.x; a0.y += v.y;
    }
    float r = __ldg(&inv_deg[warp]);
    float2 acc;
    acc.x = ((a0.x + a1.x) + (a2.x + a3.x)) * r;
    acc.y = ((a0.y + a1.y) + (a2.y + a3.y)) * r;
    mean[(size_t)warp * 32 + lane] = acc;
}

// ---------------------------------------------------------------------------
// Fused SAGE layer: out[n] = (relu?)( x[n] @ Wself + mean[n] @ Wneigh + b )
// Block: 256 threads. Tile: 64 nodes. Thread = 4 nodes x 4 output cols.
// ---------------------------------------------------------------------------
#define SAGE_SMEM_FLOATS (4096 + 4096 + 64 + 4096 + 4096)
#define SAGE_SMEM_BYTES  (SAGE_SMEM_FLOATS * 4)

__global__ void __launch_bounds__(256) sage_kernel(
    const float* __restrict__ hin,
    const float* __restrict__ Wself,
    const float* __restrict__ Wneigh,
    const float* __restrict__ bias,
    const float4* __restrict__ mean4,
    float* __restrict__ hout,
    int n_nodes, int do_relu)
{
    extern __shared__ float sm[];
    float* sWs = sm;                    // [64][64]
    float* sWn = sm + 4096;             // [64][64]
    float* sB  = sm + 8192;             // [64]
    float* sX  = sm + 8256;             // [64 nodes][64]
    float* sM  = sm + 8256 + 4096;      // [64 nodes][64]

    const int tid = threadIdx.x;

    for (int i = tid; i < 4096; i += 256) {
        sWs[i] = Wself[i];
        sWn[i] = Wneigh[i];
    }
    if (tid < 64) sB[tid] = bias[tid];
    __syncthreads();

    const int cg  = tid & 15;   // column group: cols [cg*4, cg*4+4)
    const int row = tid >> 4;   // thread row: nodes [row*4, row*4+4) within tile

    const int numTiles = (n_nodes + 63) >> 6;
    for (int tile = blockIdx.x; tile < numTiles; tile += gridDim.x) {
        const int node0 = tile << 6;

        for (int i = tid; i < 1024; i += 256) {       // float4 idx in [64][16]
            int nl = i >> 4;
            int c4 = i & 15;
            int n = node0 + nl;
            float4 xv = make_float4(0.f, 0.f, 0.f, 0.f);
            float4 mv = make_float4(0.f, 0.f, 0.f, 0.f);
            if (n < n_nodes) {
                xv = __ldg((const float4*)hin + (size_t)n * 16 + c4);
                mv = __ldg(&mean4[(size_t)n * 16 + c4]);
            }
            ((float4*)sX)[i] = xv;
            ((float4*)sM)[i] = mv;
        }
        __syncthreads();

        float4 bv = ((float4*)sB)[cg];
        float4 acc[4];
#pragma unroll
        for (int t4 = 0; t4 < 4; t4++) acc[t4] = bv;

#pragma unroll 4
        for (int k = 0; k < D; k++) {
            float4 ws = ((const float4*)sWs)[k * 16 + cg];
            float4 wn = ((const float4*)sWn)[k * 16 + cg];
#pragma unroll
            for (int t4 = 0; t4 < 4; t4++) {
                int nl = row * 4 + t4;
                float xv = sX[nl * D + k];
                float mv = sM[nl * D + k];
                acc[t4].x = fmaf(xv, ws.x, fmaf(mv, wn.x, acc[t4].x));
                acc[t4].y = fmaf(xv, ws.y, fmaf(mv, wn.y, acc[t4].y));
                acc[t4].z = fmaf(xv, ws.z, fmaf(mv, wn.z, acc[t4].z));
                acc[t4].w = fmaf(xv, ws.w, fmaf(mv, wn.w, acc[t4].w));
            }
        }

#pragma unroll
        for (int t4 = 0; t4 < 4; t4++) {
            int n = node0 + row * 4 + t4;
            if (n < n_nodes) {
                float4 o = acc[t4];
                if (do_relu) {
                    o.x = fmaxf(o.x, 0.f);
                    o.y = fmaxf(o.y, 0.f);
                    o.z = fmaxf(o.z, 0.f);
                    o.w = fmaxf(o.w, 0.f);
                }
                ((float4*)hout)[(size_t)n * 16 + cg] = o;
            }
        }
        __syncthreads();
    }
}

// ---------------------------------------------------------------------------
// Launch sequence (all graph-capturable).
// ---------------------------------------------------------------------------
extern "C" void kernel_launch(void* const* d_in, const int* in_sizes, int n_in,
                              void* d_out, int out_size) {
    const float* x   = (const float*)d_in[0];
    const int*   src = (const int*)d_in[1];
    const int*   dst = (const int*)d_in[2];
    const float* W1s = (const float*)d_in[3];
    const float* W1n = (const float*)d_in[4];
    const float* b1  = (const float*)d_in[5];
    const float* W2s = (const float*)d_in[6];
    const float* W2n = (const float*)d_in[7];
    const float* b2  = (const float*)d_in[8];
    float* out = (float*)d_out;

    const int N = in_sizes[0] / D;
    const int E = in_sizes[1];

    float4* h1_4; float4* mean4; int* degi; int* row_start; int* cursor;
    float* inv_deg; int* esrc; int* bsum; int* boff;
    cudaGetSymbolAddress((void**)&h1_4,      g_h1_4);
    cudaGetSymbolAddress((void**)&mean4,     g_mean4);
    cudaGetSymbolAddress((void**)&degi,      g_degi);
    cudaGetSymbolAddress((void**)&row_start, g_row_start);
    cudaGetSymbolAddress((void**)&cursor,    g_cursor);
    cudaGetSymbolAddress((void**)&inv_deg,   g_inv_deg);
    cudaGetSymbolAddress((void**)&esrc,      g_esrc);
    cudaGetSymbolAddress((void**)&bsum,      g_block_sum);
    cudaGetSymbolAddress((void**)&boff,      g_block_off);
    float* h1 = (float*)h1_4;

    cudaFuncSetAttribute(sage_kernel,
                         cudaFuncAttributeMaxDynamicSharedMemorySize,
                         SAGE_SMEM_BYTES);

    const int nbN = (N + 255) / 256;         // node-grained blocks
    const int nbE = (E + 255) / 256;         // edge-grained blocks
    const int nbG = (N * 32 + 255) / 256;    // gather: one warp per node
    const int nbS = (N + 63) / 64;           // sage tiles

    // CSR build (by destination)
    zero_deg_kernel<<<nbN, 256>>>(degi, N);
    count_kernel<<<nbE, 256>>>(dst, degi, E);
    scan1_kernel<<<nbN, 256>>>(degi, row_start, bsum, N);
    scan2_kernel<<<1, 256>>>(bsum, boff, nbN);
    scan3_kernel<<<nbN, 256>>>(row_start, cursor, inv_deg, degi, boff, N, E);
    fill_kernel<<<nbE, 256>>>(src, dst, cursor, esrc, E);

    // Layer 1
    gather_kernel<<<nbG, 256>>>((const float2*)x, row_start, esrc, inv_deg,
                                (float2*)mean4, N);
    sage_kernel<<<nbS, 256, SAGE_SMEM_BYTES>>>(x, W1s, W1n, b1, mean4, h1, N, 1);

    // Layer 2
    gather_kernel<<<nbG, 256>>>((const float2*)h1, row_start, esrc, inv_deg,
                                (float2*)mean4, N);
    sage_kernel<<<nbS, 256, SAGE_SMEM_BYTES>>>(h1, W2s, W2n, b2, mean4, out, N, 0);
}